// round 1
// baseline (speedup 1.0000x reference)
#include <cuda_runtime.h>
#include <math.h>

// Problem constants (fixed by the dataset)
#define NCLS 21
#define C    256
#define HW   16384
#define B    8
#define NPIX (B*HW)            // 131072
#define CAPW 1024              // weak candidates/class capacity (expected ~310)
#define CAPS 8192              // strong candidates/class capacity (expected ~6220)
#define EPSF 1e-6f
#define NEGF -1e30f

// ---------------- device scratch (no allocations allowed) ----------------
__device__ float g_pn[NCLS*C];                    // normalized prototypes
__device__ float g_wsum[NCLS*C];                  // per-class feature sums (weak/conf)
__device__ int   g_cnt_w[NCLS];
__device__ int   g_cnt_s[NCLS];
__device__ unsigned long long g_wkeys[NCLS*CAPW]; // (sortable val, ~idx) keys
__device__ unsigned long long g_skeys[NCLS*CAPS];
__device__ int   g_widx[NCLS*16];
__device__ int   g_sidx[NCLS*256];
__device__ int   g_kw[NCLS];
__device__ int   g_ks[NCLS];
__device__ float g_sim_sum;
__device__ int   g_count;

__device__ __forceinline__ unsigned long long make_key(float v, int idx) {
    unsigned u = __float_as_uint(v);
    u = (u & 0x80000000u) ? ~u : (u | 0x80000000u);   // order-preserving float->uint
    // high: value (desc). low: ~idx so equal values pick SMALLER index first (jax tie-break)
    return ((unsigned long long)u << 32) | (unsigned long long)(0xFFFFFFFFu - (unsigned)idx);
}
__device__ __forceinline__ int key_idx(unsigned long long k) {
    return (int)(0xFFFFFFFFu - (unsigned)(k & 0xFFFFFFFFull));
}

// ---------------- K0: init — normalize protos, zero scratch ----------------
__global__ void init_kernel(const float* __restrict__ bank) {
    int k = blockIdx.x;          // 21 blocks
    int t = threadIdx.x;         // 256 threads
    float v = bank[k*C + t];
    // block reduce sum of squares
    float s2 = v * v;
    #pragma unroll
    for (int o = 16; o; o >>= 1) s2 += __shfl_down_sync(0xFFFFFFFFu, s2, o);
    __shared__ float sred[8];
    __shared__ float sinv;
    if ((t & 31) == 0) sred[t >> 5] = s2;
    __syncthreads();
    if (t == 0) {
        float tot = 0.f;
        #pragma unroll
        for (int w = 0; w < 8; w++) tot += sred[w];
        sinv = 1.0f / fmaxf(sqrtf(tot), EPSF);
    }
    __syncthreads();
    g_pn[k*C + t]   = v * sinv;
    g_wsum[k*C + t] = 0.f;
    if (k == 0) {
        if (t < NCLS) { g_cnt_w[t] = 0; g_cnt_s[t] = 0; }
        if (t == 0)   { g_sim_sum = 0.f; g_count = 0; }
    }
}

// ---------------- K1: fused per-pixel pass ----------------
// per pixel: dot(fw, pn[seg]), dot(fs, pn[seg]), norms, candidate compaction,
// and wsum accumulation (confident pixels only).
__global__ __launch_bounds__(256) void main_kernel(
    const float* __restrict__ fw, const float* __restrict__ fs,
    const float* __restrict__ prob, const int* __restrict__ pred,
    const int* __restrict__ ign)
{
    __shared__ float spn[NCLS*257];   // padded stride 257 -> conflict-free divergent LDS
    for (int i = threadIdx.x; i < NCLS*C; i += blockDim.x) {
        int kk = i >> 8, cc = i & 255;
        spn[kk*257 + cc] = g_pn[i];
    }
    __syncthreads();

    int n = blockIdx.x * blockDim.x + threadIdx.x;   // 512*256 = 131072
    int b = n >> 14, p = n & (HW-1);
    int seg = pred[n];
    bool valid = (ign[n] != 255);
    bool conf  = valid && (prob[n] > 0.95f);

    const float* bw = fw + (size_t)b*C*HW + p;
    const float* bs = fs + (size_t)b*C*HW + p;
    const float* pr = spn + seg*257;
    float* ws = &g_wsum[seg*C];

    float dw = 0.f, ds = 0.f, qw = 0.f, qs = 0.f;
    #pragma unroll 8
    for (int c = 0; c < C; c++) {
        float vw = bw[(size_t)c*HW];
        float vs = bs[(size_t)c*HW];
        float pv = pr[c];
        dw = fmaf(vw, pv, dw);  qw = fmaf(vw, vw, qw);
        ds = fmaf(vs, pv, ds);  qs = fmaf(vs, vs, qs);
        if (conf) atomicAdd(&ws[c], vw);
    }
    float simw = dw / fmaxf(sqrtf(qw), EPSF);
    float sims = ds / fmaxf(sqrtf(qs), EPSF);

    if (conf) {
        int pos = atomicAdd(&g_cnt_w[seg], 1);
        if (pos < CAPW) g_wkeys[seg*CAPW + pos] = make_key(simw, n);
    }
    if (valid) {
        int pos = atomicAdd(&g_cnt_s[seg], 1);
        if (pos < CAPS) g_skeys[seg*CAPS + pos] = make_key(-sims, n);
    }
}

// ---------------- K2: per-class bitonic sort (descending), top-k extract ----------------
// blocks 0..20: weak (S=1024). blocks 21..41: strong (S=8192). 512 threads.
__global__ __launch_bounds__(512) void sort_kernel() {
    extern __shared__ unsigned long long keys[];
    int blk = blockIdx.x;
    bool weak = (blk < NCLS);
    int k = weak ? blk : blk - NCLS;
    int S = weak ? 1024 : 8192;
    const unsigned long long* src = weak ? &g_wkeys[k*CAPW] : &g_skeys[k*CAPS];
    int cnt = weak ? g_cnt_w[k] : g_cnt_s[k];
    if (cnt > S) cnt = S;

    for (int i = threadIdx.x; i < S; i += blockDim.x)
        keys[i] = (i < cnt) ? src[i] : 0ull;
    __syncthreads();

    for (int kk = 2; kk <= S; kk <<= 1) {
        for (int j = kk >> 1; j > 0; j >>= 1) {
            for (int i = threadIdx.x; i < S; i += blockDim.x) {
                int ixj = i ^ j;
                if (ixj > i) {
                    unsigned long long a = keys[i], bb = keys[ixj];
                    bool up = ((i & kk) == 0);             // descending overall
                    if (up ? (a < bb) : (a > bb)) { keys[i] = bb; keys[ixj] = a; }
                }
            }
            __syncthreads();
        }
    }
    if (weak) {
        if (threadIdx.x == 0) g_kw[k] = (cnt < 16) ? cnt : 16;
        if (threadIdx.x < 16) g_widx[k*16 + threadIdx.x] = key_idx(keys[threadIdx.x]);
    } else {
        if (threadIdx.x == 0) g_ks[k] = (cnt < 256) ? cnt : 256;
        if (threadIdx.x < 256) g_sidx[k*256 + threadIdx.x] = key_idx(keys[threadIdx.x]);
    }
}

// ---------------- K3: per-class loss ----------------
__global__ __launch_bounds__(256) void loss_kernel(
    const float* __restrict__ fw, const float* __restrict__ fs)
{
    int k = blockIdx.x;        // 21 blocks
    int t = threadIdx.x;       // 256 threads (= channel in phase A, = strong slot in B)
    __shared__ float wn[C*16];         // wn[c*16 + r] : normalized weak vectors (transposed)
    __shared__ float cosm[16*256];
    __shared__ float sred[8];
    __shared__ float sbcast;
    __shared__ float maxv[16];

    int kw = g_kw[k], ks = g_ks[k];

    // Phase A: gather + normalize weak vectors into smem
    for (int r = 0; r < 16; r++) {
        float v = 0.f;
        if (r < kw) {
            int nw = g_widx[k*16 + r];
            int bw = nw >> 14, pw = nw & (HW-1);
            v = fw[((size_t)bw*C + t)*HW + pw];
        }
        float s2 = v * v;
        #pragma unroll
        for (int o = 16; o; o >>= 1) s2 += __shfl_down_sync(0xFFFFFFFFu, s2, o);
        if ((t & 31) == 0) sred[t >> 5] = s2;
        __syncthreads();
        if (t == 0) {
            float tot = 0.f;
            #pragma unroll
            for (int w = 0; w < 8; w++) tot += sred[w];
            sbcast = 1.0f / fmaxf(sqrtf(tot), EPSF);
        }
        __syncthreads();
        wn[t*16 + r] = v * sbcast;
        __syncthreads();
    }

    // Phase B: each thread = one strong vector; dot vs all 16 weak rows
    float acc[16];
    #pragma unroll
    for (int w = 0; w < 16; w++) acc[w] = 0.f;
    float q = 0.f;
    if (t < ks) {
        int ns = g_sidx[k*256 + t];
        int bsn = ns >> 14, ps = ns & (HW-1);
        const float* base = fs + (size_t)bsn*C*HW + ps;
        #pragma unroll 4
        for (int c = 0; c < C; c++) {
            float v = base[(size_t)c*HW];
            q = fmaf(v, v, q);
            const float4* wr = (const float4*)&wn[c*16];   // broadcast LDS.128
            #pragma unroll
            for (int g = 0; g < 4; g++) {
                float4 w4 = wr[g];
                acc[g*4+0] = fmaf(v, w4.x, acc[g*4+0]);
                acc[g*4+1] = fmaf(v, w4.y, acc[g*4+1]);
                acc[g*4+2] = fmaf(v, w4.z, acc[g*4+2]);
                acc[g*4+3] = fmaf(v, w4.w, acc[g*4+3]);
            }
        }
    }
    float inv = 1.0f / fmaxf(sqrtf(q), EPSF);
    __syncthreads();   // wn reads done before reuse of smem region? (cosm is separate; sync for correctness of maxv path)
    #pragma unroll
    for (int w = 0; w < 16; w++)
        cosm[w*256 + t] = (t < ks) ? acc[w]*inv : NEGF;
    __syncthreads();

    // max over strong slots per weak row (8 warps, 2 rows each)
    int wid = t >> 5, lid = t & 31;
    for (int w = wid; w < 16; w += 8) {
        float m = NEGF;
        for (int s = lid; s < 256; s += 32) m = fmaxf(m, cosm[w*256 + s]);
        #pragma unroll
        for (int o = 16; o; o >>= 1) m = fmaxf(m, __shfl_down_sync(0xFFFFFFFFu, m, o));
        if (lid == 0) maxv[w] = m;
    }
    __syncthreads();

    if (t == 0 && kw > 0 && ks > 0) {
        float ssum = 0.f;
        for (int j = 0; j < kw; j++) {
            int r = (j == 0) ? 0 : (j - 1);   // ranks = max(arange(16)-1, 0)
            ssum += maxv[r];
        }
        atomicAdd(&g_sim_sum, ssum);
        atomicAdd(&g_count, ks);
    }
}

// ---------------- K4: finalize — loss + EMA memory bank ----------------
__global__ void final_kernel(const float* __restrict__ bank, float* __restrict__ out,
                             int out_size) {
    int i = blockIdx.x * blockDim.x + threadIdx.x;   // 0..5375
    if (i < NCLS*C && (1 + i) < out_size) {
        int k = i >> 8;
        int nw = g_cnt_w[k];
        float pv = bank[i];
        float o = pv;
        if (nw > 0) {
            float mean = g_wsum[i] / (float)((nw > 1) ? nw : 1);
            o = 0.99f * pv + 0.01f * mean;
        }
        out[1 + i] = o;
    }
    if (i == 0) {
        int cnt = g_count;
        out[0] = (cnt > 0) ? (1.0f - g_sim_sum / (float)cnt) : 0.0f;
    }
}

// ---------------- launch ----------------
extern "C" void kernel_launch(void* const* d_in, const int* in_sizes, int n_in,
                              void* d_out, int out_size) {
    const float* fw   = (const float*)d_in[0];
    const float* fs   = (const float*)d_in[1];
    const float* prob = (const float*)d_in[2];
    const float* bank = (const float*)d_in[3];
    const int*   pred = (const int*)d_in[4];
    const int*   ign  = (const int*)d_in[5];
    float* out = (float*)d_out;

    cudaFuncSetAttribute(sort_kernel, cudaFuncAttributeMaxDynamicSharedMemorySize, 65536);

    init_kernel<<<NCLS, 256>>>(bank);
    main_kernel<<<NPIX/256, 256>>>(fw, fs, prob, pred, ign);
    sort_kernel<<<2*NCLS, 512, 65536>>>();
    loss_kernel<<<NCLS, 256>>>(fw, fs);
    final_kernel<<<(NCLS*C + 255)/256, 256>>>(bank, out, out_size);
}

// round 2
// speedup vs baseline: 1.9996x; 1.9996x over previous
#include <cuda_runtime.h>
#include <math.h>

#define NCLS 21
#define C    256
#define HW   16384
#define B    8
#define NPIX (B*HW)
#define CAPW 2048
#define CAPS 8192
#define EPSF 1e-6f
#define NEGF -1e30f
#define NBINS 4096
#define BCAP 1024

// ---------------- device scratch ----------------
__device__ float g_pn[NCLS*C];
__device__ float g_wsum[NCLS*C];
__device__ int   g_cnt_w[NCLS];
__device__ int   g_cnt_s[NCLS];
__device__ unsigned long long g_wkeys[NCLS*CAPW];
__device__ unsigned long long g_skeys[NCLS*CAPS];
__device__ int   g_widx[NCLS*16];
__device__ int   g_sidx[NCLS*256];
__device__ int   g_kw[NCLS];
__device__ int   g_ks[NCLS];
__device__ float g_wn[NCLS*C*16];        // rank-mapped normalized weak vectors
__device__ unsigned g_maxv[NCLS*16];     // encoded float max per (class, weak row)

__device__ __forceinline__ unsigned long long make_key(float v, int idx) {
    unsigned u = __float_as_uint(v);
    u = (u & 0x80000000u) ? ~u : (u | 0x80000000u);
    return ((unsigned long long)u << 32) | (unsigned long long)(0xFFFFFFFFu - (unsigned)idx);
}
__device__ __forceinline__ int key_idx(unsigned long long k) {
    return (int)(0xFFFFFFFFu - (unsigned)(k & 0xFFFFFFFFull));
}
__device__ __forceinline__ unsigned fenc(float f) {
    unsigned u = __float_as_uint(f);
    return (u >> 31) ? ~u : (u | 0x80000000u);
}
__device__ __forceinline__ float fdec(unsigned u) {
    return __uint_as_float((u >> 31) ? (u & 0x7FFFFFFFu) : ~u);
}

// ---------------- K0: init ----------------
__global__ void init_kernel(const float* __restrict__ bank) {
    int k = blockIdx.x, t = threadIdx.x;
    float v = bank[k*C + t];
    float s2 = v * v;
    #pragma unroll
    for (int o = 16; o; o >>= 1) s2 += __shfl_down_sync(0xFFFFFFFFu, s2, o);
    __shared__ float sred[8];
    __shared__ float sinv;
    if ((t & 31) == 0) sred[t >> 5] = s2;
    __syncthreads();
    if (t == 0) {
        float tot = 0.f;
        #pragma unroll
        for (int w = 0; w < 8; w++) tot += sred[w];
        sinv = 1.0f / fmaxf(sqrtf(tot), EPSF);
    }
    __syncthreads();
    g_pn[k*C + t]   = v * sinv;
    g_wsum[k*C + t] = 0.f;
    if (t < 16) g_maxv[k*16 + t] = 0u;
    if (k == 0 && t < NCLS) { g_cnt_w[t] = 0; g_cnt_s[t] = 0; }
}

// ---------------- K1: fused per-pixel pass (pure loads+FMA) ----------------
__global__ __launch_bounds__(256) void main_kernel(
    const float* __restrict__ fw, const float* __restrict__ fs,
    const float* __restrict__ prob, const int* __restrict__ pred,
    const int* __restrict__ ign)
{
    __shared__ float spn[NCLS*257];
    __shared__ int scw[NCLS], scs[NCLS], sbw[NCLS], sbs[NCLS];
    for (int i = threadIdx.x; i < NCLS*C; i += blockDim.x)
        spn[(i >> 8)*257 + (i & 255)] = g_pn[i];
    if (threadIdx.x < NCLS) { scw[threadIdx.x] = 0; scs[threadIdx.x] = 0; }
    __syncthreads();

    int n = blockIdx.x * blockDim.x + threadIdx.x;
    int b = n >> 14, p = n & (HW-1);
    int seg = pred[n];
    bool valid = (ign[n] != 255);
    bool conf  = valid && (prob[n] > 0.95f);

    const float* bw = fw + (size_t)b*C*HW + p;
    const float* bs = fs + (size_t)b*C*HW + p;
    const float* pr = spn + seg*257;

    float dw = 0.f, ds = 0.f, qw = 0.f, qs = 0.f;
    #pragma unroll 8
    for (int c = 0; c < C; c++) {
        float vw = bw[(size_t)c*HW];
        float vs = bs[(size_t)c*HW];
        float pv = pr[c];
        dw = fmaf(vw, pv, dw);  qw = fmaf(vw, vw, qw);
        ds = fmaf(vs, pv, ds);  qs = fmaf(vs, vs, qs);
    }
    float simw = dw / fmaxf(sqrtf(qw), EPSF);
    float sims = ds / fmaxf(sqrtf(qs), EPSF);

    int lpw = -1, lps = -1;
    if (conf)  lpw = atomicAdd(&scw[seg], 1);
    if (valid) lps = atomicAdd(&scs[seg], 1);
    __syncthreads();
    if (threadIdx.x < NCLS) {
        sbw[threadIdx.x] = atomicAdd(&g_cnt_w[threadIdx.x], scw[threadIdx.x]);
        sbs[threadIdx.x] = atomicAdd(&g_cnt_s[threadIdx.x], scs[threadIdx.x]);
    }
    __syncthreads();
    if (conf) {
        int pos = sbw[seg] + lpw;
        if (pos < CAPW) g_wkeys[seg*CAPW + pos] = make_key(simw, n);
    }
    if (valid) {
        int pos = sbs[seg] + lps;
        if (pos < CAPS) g_skeys[seg*CAPS + pos] = make_key(-sims, n);
    }
}

// ---------------- K2: selection ----------------
// blocks 0..20: weak (full bitonic over 2048, ordered top-16)
// blocks 21..41: strong (histogram radix-select, unordered top-256 set)
__global__ __launch_bounds__(256) void select_kernel() {
    __shared__ unsigned long long skeys[2048];   // weak bitonic
    __shared__ int hist[NBINS];
    __shared__ unsigned long long bkeys[BCAP];
    __shared__ int gsum[256];
    __shared__ int sh_T, sh_a, sh_m, sh_out, sh_bnd;

    int blk = blockIdx.x, tid = threadIdx.x;
    if (blk < NCLS) {
        // ---- weak: bitonic sort 2048 desc ----
        int k = blk;
        int cnt = g_cnt_w[k]; if (cnt > CAPW) cnt = CAPW;
        for (int i = tid; i < 2048; i += 256)
            skeys[i] = (i < cnt) ? g_wkeys[k*CAPW + i] : 0ull;
        __syncthreads();
        for (int kk = 2; kk <= 2048; kk <<= 1) {
            for (int j = kk >> 1; j > 0; j >>= 1) {
                for (int i = tid; i < 2048; i += 256) {
                    int ixj = i ^ j;
                    if (ixj > i) {
                        unsigned long long a = skeys[i], bb = skeys[ixj];
                        bool up = ((i & kk) == 0);
                        if (up ? (a < bb) : (a > bb)) { skeys[i] = bb; skeys[ixj] = a; }
                    }
                }
                __syncthreads();
            }
        }
        if (tid == 0) g_kw[k] = (cnt < 16) ? cnt : 16;
        if (tid < 16) g_widx[k*16 + tid] = key_idx(skeys[tid]);
    } else {
        // ---- strong: radix select top-256 set ----
        int k = blk - NCLS;
        int cnt = g_cnt_s[k]; if (cnt > CAPS) cnt = CAPS;
        int need = (cnt < 256) ? cnt : 256;
        for (int i = tid; i < NBINS; i += 256) hist[i] = 0;
        if (tid == 0) { sh_out = 0; sh_bnd = 0; }
        __syncthreads();
        const unsigned long long* src = &g_skeys[k*CAPS];
        for (int i = tid; i < cnt; i += 256) {
            int bin = (int)(src[i] >> 52);
            atomicAdd(&hist[bin], 1);
        }
        __syncthreads();
        { int s = 0;
          #pragma unroll 4
          for (int b2 = 0; b2 < 16; b2++) s += hist[tid*16 + b2];
          gsum[tid] = s; }
        __syncthreads();
        if (tid == 0) {
            int acc = 0, G = 0;
            for (int g = 255; g >= 0; g--) {
                if (acc + gsum[g] >= need) { G = g; break; }
                acc += gsum[g];
            }
            int T = G*16;
            for (int b2 = G*16 + 15; b2 >= G*16; b2--) {
                if (acc + hist[b2] >= need) { T = b2; break; }
                acc += hist[b2];
            }
            sh_T = T; sh_a = acc; sh_m = need - acc;
        }
        __syncthreads();
        int T = sh_T;
        for (int i = tid; i < cnt; i += 256) {
            unsigned long long key = src[i];
            int bin = (int)(key >> 52);
            if (bin > T) {
                int pos = atomicAdd(&sh_out, 1);
                g_sidx[k*256 + pos] = key_idx(key);
            } else if (bin == T) {
                int pos = atomicAdd(&sh_bnd, 1);
                if (pos < BCAP) bkeys[pos] = key;
            }
        }
        __syncthreads();
        int bnd = sh_bnd; if (bnd > BCAP) bnd = BCAP;
        int P = 1; while (P < bnd) P <<= 1;
        for (int i = tid; i < P; i += 256) if (i >= bnd) bkeys[i] = 0ull;
        __syncthreads();
        for (int kk = 2; kk <= P; kk <<= 1) {
            for (int j = kk >> 1; j > 0; j >>= 1) {
                for (int i = tid; i < P; i += 256) {
                    int ixj = i ^ j;
                    if (ixj > i) {
                        unsigned long long a = bkeys[i], bb = bkeys[ixj];
                        bool up = ((i & kk) == 0);
                        if (up ? (a < bb) : (a > bb)) { bkeys[i] = bb; bkeys[ixj] = a; }
                    }
                }
                __syncthreads();
            }
        }
        if (tid < sh_m) g_sidx[k*256 + sh_a + tid] = key_idx(bkeys[tid]);
        if (tid == 0) g_ks[k] = need;
    }
}

// ---------------- K3a: wsum gather (grid 21 x 8) ----------------
__global__ __launch_bounds__(256) void wsum_kernel(const float* __restrict__ fw) {
    int k = blockIdx.x, ch = blockIdx.y, t = threadIdx.x;
    int cnt = g_cnt_w[k]; if (cnt > CAPW) cnt = CAPW;
    int per = (cnt + 7) / 8;
    int lo = ch * per, hi = lo + per; if (hi > cnt) hi = cnt;
    float acc = 0.f;
    for (int i = lo; i < hi; i++) {
        int n = key_idx(g_wkeys[k*CAPW + i]);
        int b = n >> 14, p = n & (HW-1);
        acc += fw[((size_t)b*C + t)*HW + p];
    }
    if (hi > lo) atomicAdd(&g_wsum[k*C + t], acc);
}

// ---------------- K3b: normalized rank-mapped weak vectors ----------------
__global__ __launch_bounds__(256) void wn_kernel(const float* __restrict__ fw) {
    int k = blockIdx.x, t = threadIdx.x;
    __shared__ float sred[8];
    __shared__ float sbcast;
    int kw = g_kw[k];
    for (int r = 0; r < 16; r++) {
        int rr = (r == 0) ? 0 : (r - 1);   // ranks mapping
        float v = 0.f;
        if (r < kw) {
            int n = g_widx[k*16 + rr];
            int b = n >> 14, p = n & (HW-1);
            v = fw[((size_t)b*C + t)*HW + p];
        }
        float s2 = v * v;
        #pragma unroll
        for (int o = 16; o; o >>= 1) s2 += __shfl_down_sync(0xFFFFFFFFu, s2, o);
        if ((t & 31) == 0) sred[t >> 5] = s2;
        __syncthreads();
        if (t == 0) {
            float tot = 0.f;
            #pragma unroll
            for (int w = 0; w < 8; w++) tot += sred[w];
            sbcast = 1.0f / fmaxf(sqrtf(tot), EPSF);
        }
        __syncthreads();
        g_wn[(k*C + t)*16 + r] = v * sbcast;
        __syncthreads();
    }
}

// ---------------- K4: loss (grid 21 x 8, 32 strong slots/block, 8 thr/slot) ----
__global__ __launch_bounds__(256) void loss_kernel(const float* __restrict__ fs) {
    int k = blockIdx.x, chunk = blockIdx.y, tid = threadIdx.x;
    __shared__ float swn[C*18];        // padded stride 18 -> conflict-free float2
    __shared__ unsigned smax[16];
    for (int i = tid; i < C*16; i += 256) {
        int c = i >> 4, r = i & 15;
        swn[c*18 + r] = g_wn[k*C*16 + i];
    }
    if (tid < 16) smax[tid] = 0u;
    __syncthreads();

    int ks = g_ks[k];
    int slot = tid >> 3, j = tid & 7;
    int s = chunk*32 + slot;

    float acc[16];
    #pragma unroll
    for (int w = 0; w < 16; w++) acc[w] = 0.f;
    float q = 0.f;
    bool active = (s < ks);
    if (active) {
        int n = g_sidx[k*256 + s];
        int b = n >> 14, p = n & (HW-1);
        const float* base = fs + (size_t)b*C*HW + p;
        #pragma unroll 4
        for (int cc = 0; cc < 32; cc++) {
            int c = cc*8 + j;
            float v = base[(size_t)c*HW];
            q = fmaf(v, v, q);
            const float2* row = (const float2*)&swn[c*18];
            #pragma unroll
            for (int g = 0; g < 8; g++) {
                float2 w2 = row[g];
                acc[g*2+0] = fmaf(v, w2.x, acc[g*2+0]);
                acc[g*2+1] = fmaf(v, w2.y, acc[g*2+1]);
            }
        }
    }
    // reduce over the 8 cooperating lanes (xor stays within group)
    #pragma unroll
    for (int o = 4; o; o >>= 1) {
        q += __shfl_xor_sync(0xFFFFFFFFu, q, o);
        #pragma unroll
        for (int w = 0; w < 16; w++)
            acc[w] += __shfl_xor_sync(0xFFFFFFFFu, acc[w], o);
    }
    if (active && j == 0) {
        float inv = 1.0f / fmaxf(sqrtf(q), EPSF);
        #pragma unroll
        for (int w = 0; w < 16; w++)
            atomicMax(&smax[w], fenc(acc[w] * inv));
    }
    __syncthreads();
    if (tid < 16 && ks > 0) atomicMax(&g_maxv[k*16 + tid], smax[tid]);
}

// ---------------- K5: finalize ----------------
__global__ void final_kernel(const float* __restrict__ bank, float* __restrict__ out,
                             int out_size) {
    int i = blockIdx.x * blockDim.x + threadIdx.x;
    if (i < NCLS*C && (1 + i) < out_size) {
        int k = i >> 8;
        int nw = g_cnt_w[k];
        float pv = bank[i];
        float o = pv;
        if (nw > 0) {
            float mean = g_wsum[i] / (float)((nw > 1) ? nw : 1);
            o = 0.99f * pv + 0.01f * mean;
        }
        out[1 + i] = o;
    }
    if (i == 0) {
        float ssum = 0.f;
        long long cnt = 0;
        for (int k = 0; k < NCLS; k++) {
            int kw = g_kw[k], ks = g_ks[k];
            if (kw > 0 && ks > 0) {
                for (int r = 0; r < kw; r++) ssum += fdec(g_maxv[k*16 + r]);
                cnt += ks;
            }
        }
        out[0] = (cnt > 0) ? (1.0f - ssum / (float)cnt) : 0.0f;
    }
}

// ---------------- launch ----------------
extern "C" void kernel_launch(void* const* d_in, const int* in_sizes, int n_in,
                              void* d_out, int out_size) {
    const float* fw   = (const float*)d_in[0];
    const float* fs   = (const float*)d_in[1];
    const float* prob = (const float*)d_in[2];
    const float* bank = (const float*)d_in[3];
    const int*   pred = (const int*)d_in[4];
    const int*   ign  = (const int*)d_in[5];
    float* out = (float*)d_out;

    init_kernel<<<NCLS, 256>>>(bank);
    main_kernel<<<NPIX/256, 256>>>(fw, fs, prob, pred, ign);
    select_kernel<<<2*NCLS, 256>>>();
    wsum_kernel<<<dim3(NCLS, 8), 256>>>(fw);
    wn_kernel<<<NCLS, 256>>>(fw);
    loss_kernel<<<dim3(NCLS, 8), 256>>>(fs);
    final_kernel<<<(NCLS*C + 255)/256, 256>>>(bank, out, out_size);
}